// round 1
// baseline (speedup 1.0000x reference)
#include <cuda_runtime.h>

constexpr int kB = 8, kN = 4096, kD = 1024, kH = 1024, kNQ = 64;
constexpr int kTOPK = 1024, kTWOH = 2048;
constexpr int KC = 32;     // K-chunk per smem stage
constexpr int AP = 132;    // A smem pitch (floats) — padded vs 128 to kill STS conflicts
constexpr int BP = 68;     // B smem pitch (floats)

// ---------------- scratch (device globals; no allocations allowed) ----------------
__device__ float g_QW[kNQ * kD];            // (query_embed @ key_w^T) / sqrt(H)
__device__ float g_qb[kNQ];                 // (query_embed @ key_b) / sqrt(H)
__device__ float g_bias[kB * kN];           // density bias per token
__device__ float g_S[(size_t)kB * kNQ * kN];// scores [b][q][n]
__device__ float g_lse[kB * kNQ];           // logsumexp per (b,q)
__device__ float g_logit[kB * kN];          // max_q (s - lse) per token
__device__ int   g_idx[kB * kTOPK];         // selected indices, ascending

// ---------------- f32x2 packed-FP32 helpers (Blackwell) ----------------
__device__ __forceinline__ unsigned long long f32x2_pack(float lo, float hi) {
    unsigned long long r;
    asm("mov.b64 %0, {%1, %2};" : "=l"(r) : "f"(lo), "f"(hi));
    return r;
}
__device__ __forceinline__ void f32x2_unpack(unsigned long long v, float& lo, float& hi) {
    asm("mov.b64 {%0, %1}, %2;" : "=f"(lo), "=f"(hi) : "l"(v));
}
__device__ __forceinline__ unsigned long long f32x2_fma(unsigned long long a,
                                                        unsigned long long b,
                                                        unsigned long long c) {
    unsigned long long d;
    asm("fma.rn.f32x2 %0, %1, %2, %3;" : "=l"(d) : "l"(a), "l"(b), "l"(c));
    return d;
}

// ---------------- shared 128x64xK tile GEMM: C[r][c] = sum_k A[r][k]*Bm[c][k] ----------------
// 256 threads: warp w handles cols 8w..8w+7; lane l handles rows 4l..4l+3.
// A rows stride 1024, Bm rows stride 1024, K = 1024.
__device__ __forceinline__ void tile_gemm_128x64(
    const float* __restrict__ A, const float* __restrict__ Bm,
    float* As, float* Bs, unsigned long long c2[4][4])
{
    const int tid = threadIdx.x;
    const int w = tid >> 5, l = tid & 31;
#pragma unroll
    for (int j = 0; j < 4; j++)
#pragma unroll
        for (int p = 0; p < 4; p++) c2[j][p] = 0ull;

    for (int k0 = 0; k0 < kD; k0 += KC) {
        // A tile 128x32 -> As[k][row] (transposed, pitch AP)
#pragma unroll
        for (int i = 0; i < 4; i++) {
            int idx = tid + i * 256;        // 1024 float4 slots
            int r = idx >> 3, c4 = idx & 7;
            float4 v = *(const float4*)(A + (size_t)r * kD + k0 + c4 * 4);
            As[(c4 * 4 + 0) * AP + r] = v.x;
            As[(c4 * 4 + 1) * AP + r] = v.y;
            As[(c4 * 4 + 2) * AP + r] = v.z;
            As[(c4 * 4 + 3) * AP + r] = v.w;
        }
        // B tile 64x32 -> Bs[k][col] (pitch BP)
#pragma unroll
        for (int i = 0; i < 2; i++) {
            int idx = tid + i * 256;        // 512 float4 slots
            int q = idx >> 3, c4 = idx & 7;
            float4 v = *(const float4*)(Bm + (size_t)q * kD + k0 + c4 * 4);
            Bs[(c4 * 4 + 0) * BP + q] = v.x;
            Bs[(c4 * 4 + 1) * BP + q] = v.y;
            Bs[(c4 * 4 + 2) * BP + q] = v.z;
            Bs[(c4 * 4 + 3) * BP + q] = v.w;
        }
        __syncthreads();
#pragma unroll 8
        for (int k = 0; k < KC; k++) {
            float4 a4 = *(const float4*)(As + k * AP + 4 * l);
            ulonglong2 b01 = *(const ulonglong2*)(Bs + k * BP + 8 * w);
            ulonglong2 b23 = *(const ulonglong2*)(Bs + k * BP + 8 * w + 4);
            float av[4] = {a4.x, a4.y, a4.z, a4.w};
#pragma unroll
            for (int j = 0; j < 4; j++) {
                unsigned long long a2 = f32x2_pack(av[j], av[j]);
                c2[j][0] = f32x2_fma(a2, b01.x, c2[j][0]);
                c2[j][1] = f32x2_fma(a2, b01.y, c2[j][1]);
                c2[j][2] = f32x2_fma(a2, b23.x, c2[j][2]);
                c2[j][3] = f32x2_fma(a2, b23.y, c2[j][3]);
            }
        }
        __syncthreads();
    }
}

// ---------------- 1) QW = (query_embed @ key_w^T)/32 ----------------
__global__ void __launch_bounds__(256) qw_kernel(const float* __restrict__ kw,
                                                 const float* __restrict__ qe)
{
    __shared__ float As[KC * AP];
    __shared__ float Bs[KC * BP];
    const int d0 = blockIdx.x * 128;
    unsigned long long c2[4][4];
    tile_gemm_128x64(kw + (size_t)d0 * kH, qe, As, Bs, c2);

    const int tid = threadIdx.x, w = tid >> 5, l = tid & 31;
    const int dbase = d0 + 4 * l;
#pragma unroll
    for (int p = 0; p < 4; p++) {
#pragma unroll
        for (int j = 0; j < 4; j++) {
            float x, y;
            f32x2_unpack(c2[j][p], x, y);
            g_QW[(8 * w + 2 * p + 0) * kD + dbase + j] = x * 0.03125f;
            g_QW[(8 * w + 2 * p + 1) * kD + dbase + j] = y * 0.03125f;
        }
    }
}

// ---------------- 2) qb = (query_embed @ key_b)/32 ----------------
__global__ void qb_kernel(const float* __restrict__ qe, const float* __restrict__ kb)
{
    const int q = threadIdx.x;            // 64 threads
    const float* row = qe + (size_t)q * kH;
    float s0 = 0.f, s1 = 0.f, s2 = 0.f, s3 = 0.f;
    for (int h = 0; h < kH; h += 4) {
        s0 = fmaf(row[h + 0], kb[h + 0], s0);
        s1 = fmaf(row[h + 1], kb[h + 1], s1);
        s2 = fmaf(row[h + 2], kb[h + 2], s2);
        s3 = fmaf(row[h + 3], kb[h + 3], s3);
    }
    g_qb[q] = ((s0 + s1) + (s2 + s3)) * 0.03125f;
}

// ---------------- 3) density bias: relu(d*w1 + b1) @ w2 + b2 ----------------
__global__ void __launch_bounds__(256) density_kernel(
    const float* __restrict__ dens, const float* __restrict__ w1,
    const float* __restrict__ b1, const float* __restrict__ w2,
    const float* __restrict__ b2)
{
    __shared__ float sw1[kTWOH], sb1[kTWOH], sw2[kTWOH];
    const int tid = threadIdx.x;
    for (int i = tid; i < kTWOH; i += 256) { sw1[i] = w1[i]; sb1[i] = b1[i]; sw2[i] = w2[i]; }
    __syncthreads();
    const int t = blockIdx.x * 256 + tid;
    const float d = dens[t];
    float a0 = 0.f, a1 = 0.f, a2 = 0.f, a3 = 0.f;
#pragma unroll 4
    for (int j = 0; j < kTWOH; j += 4) {
        float h0 = fmaxf(fmaf(d, sw1[j + 0], sb1[j + 0]), 0.f);
        float h1 = fmaxf(fmaf(d, sw1[j + 1], sb1[j + 1]), 0.f);
        float h2 = fmaxf(fmaf(d, sw1[j + 2], sb1[j + 2]), 0.f);
        float h3 = fmaxf(fmaf(d, sw1[j + 3], sb1[j + 3]), 0.f);
        a0 = fmaf(h0, sw2[j + 0], a0);
        a1 = fmaf(h1, sw2[j + 1], a1);
        a2 = fmaf(h2, sw2[j + 2], a2);
        a3 = fmaf(h3, sw2[j + 3], a3);
    }
    g_bias[t] = (a0 + a1) + (a2 + a3) + b2[0];
}

// ---------------- 4) scores S[b][q][n] = tf·QW^T + qb + bias ----------------
__global__ void __launch_bounds__(256) scores_kernel(const float* __restrict__ tf)
{
    __shared__ float As[KC * AP];
    __shared__ float Bs[KC * BP];
    const int b = blockIdx.y;
    const int n0 = blockIdx.x * 128;
    unsigned long long c2[4][4];
    tile_gemm_128x64(tf + ((size_t)b * kN + n0) * kD, g_QW, As, Bs, c2);

    const int tid = threadIdx.x, w = tid >> 5, l = tid & 31;
    const int nbase = n0 + 4 * l;
    float bv[4];
#pragma unroll
    for (int j = 0; j < 4; j++) bv[j] = g_bias[b * kN + nbase + j];
    float cc[4][8];
#pragma unroll
    for (int j = 0; j < 4; j++)
#pragma unroll
        for (int p = 0; p < 4; p++)
            f32x2_unpack(c2[j][p], cc[j][2 * p], cc[j][2 * p + 1]);
#pragma unroll
    for (int c = 0; c < 8; c++) {
        const int q = 8 * w + c;
        const float add = g_qb[q];
        float4 o;
        o.x = cc[0][c] + add + bv[0];
        o.y = cc[1][c] + add + bv[1];
        o.z = cc[2][c] + add + bv[2];
        o.w = cc[3][c] + add + bv[3];
        *(float4*)(g_S + ((size_t)(b * kNQ + q)) * kN + nbase) = o;
    }
}

// ---------------- 5) per-(b,q) logsumexp over n ----------------
__global__ void __launch_bounds__(256) lse_kernel()
{
    const int row = blockIdx.x;           // 0..511
    const float* s = g_S + (size_t)row * kN;
    const int tid = threadIdx.x;
    __shared__ float red[8];

    float m = -3.402823466e38f;
    for (int i = tid; i < kN; i += 256) m = fmaxf(m, s[i]);
#pragma unroll
    for (int o = 16; o; o >>= 1) m = fmaxf(m, __shfl_xor_sync(0xffffffffu, m, o));
    if ((tid & 31) == 0) red[tid >> 5] = m;
    __syncthreads();
    float mm = red[0];
#pragma unroll
    for (int i = 1; i < 8; i++) mm = fmaxf(mm, red[i]);
    __syncthreads();

    float sum = 0.f;
    for (int i = tid; i < kN; i += 256) sum += __expf(s[i] - mm);
#pragma unroll
    for (int o = 16; o; o >>= 1) sum += __shfl_xor_sync(0xffffffffu, sum, o);
    if ((tid & 31) == 0) red[tid >> 5] = sum;
    __syncthreads();
    if (tid == 0) {
        float tot = red[0];
        for (int i = 1; i < 8; i++) tot += red[i];
        g_lse[row] = mm + logf(tot);
    }
}

// ---------------- 6) importance logit = max_q (s - lse) ----------------
__global__ void __launch_bounds__(256) logit_kernel()
{
    __shared__ float ls[kNQ];
    const int tid = threadIdx.x;
    const int b = blockIdx.y;
    if (tid < kNQ) ls[tid] = g_lse[b * kNQ + tid];
    __syncthreads();
    const int n = blockIdx.x * 256 + tid;
    const float* s = g_S + (size_t)b * kNQ * kN + n;
    float best = -3.402823466e38f;
#pragma unroll 8
    for (int q = 0; q < kNQ; q++)
        best = fmaxf(best, s[(size_t)q * kN] - ls[q]);
    g_logit[b * kN + n] = best;
}

// ---------------- 7) per-batch top-1024, ascending indices ----------------
__global__ void __launch_bounds__(1024) topk_kernel()
{
    const int b = blockIdx.x;
    const int tid = threadIdx.x;
    __shared__ float sv[kN];
    __shared__ int wsum[32];
    const float* lg = g_logit + b * kN;
    for (int i = tid; i < kN; i += 1024) sv[i] = lg[i];
    __syncthreads();

    // bitonic sort, descending
    for (int k = 2; k <= kN; k <<= 1) {
        for (int j = k >> 1; j > 0; j >>= 1) {
            for (int i = tid; i < kN; i += 1024) {
                int ixj = i ^ j;
                if (ixj > i) {
                    float a = sv[i], c = sv[ixj];
                    bool descend = ((i & k) == 0);
                    bool sw = descend ? (a < c) : (a > c);
                    if (sw) { sv[i] = c; sv[ixj] = a; }
                }
            }
            __syncthreads();
        }
    }
    const float thr = sv[kTOPK - 1];

    // counts from original (unsorted) values; thread tid owns n = 4*tid..4*tid+3
    float v[4];
    int gt = 0, eq = 0;
#pragma unroll
    for (int u = 0; u < 4; u++) {
        v[u] = lg[tid * 4 + u];
        gt += (v[u] > thr);
        eq += (v[u] == thr);
    }
    int x = (gt << 16) | eq;                 // packed (gt, eq), each <= 4096
    const int lane = tid & 31, wid = tid >> 5;
#pragma unroll
    for (int o = 1; o < 32; o <<= 1) {
        int y = __shfl_up_sync(0xffffffffu, x, o);
        if (lane >= o) x += y;
    }
    if (lane == 31) wsum[wid] = x;
    __syncthreads();
    if (wid == 0) {
        int y = wsum[lane];
#pragma unroll
        for (int o = 1; o < 32; o <<= 1) {
            int z = __shfl_up_sync(0xffffffffu, y, o);
            if (lane >= o) y += z;
        }
        wsum[lane] = y;                      // inclusive scan of warp totals
    }
    __syncthreads();
    const int warpbase = (wid == 0) ? 0 : wsum[wid - 1];
    const int incl = warpbase + x;
    int gt_before = (incl >> 16) - gt;
    int eq_before = (incl & 0xffff) - eq;
    const int total_gt = wsum[31] >> 16;
    const int need_eq = kTOPK - total_gt;    // ties filled by lowest index (jax semantics)
    int* outi = g_idx + b * kTOPK;
#pragma unroll
    for (int u = 0; u < 4; u++) {
        const int n = tid * 4 + u;
        if (v[u] > thr) {
            int pos = gt_before + min(eq_before, need_eq);
            outi[pos] = n;
            gt_before++;
        } else if (v[u] == thr) {
            if (eq_before < need_eq) outi[gt_before + eq_before] = n;
            eq_before++;
        }
    }
}

// ---------------- 8) gather selected rows ----------------
__global__ void __launch_bounds__(256) gather_kernel(const float* __restrict__ tf,
                                                     float* __restrict__ out)
{
    const int b = blockIdx.y, k = blockIdx.x;
    const int row = g_idx[b * kTOPK + k];
    const float4* src = (const float4*)(tf + ((size_t)b * kN + row) * kD);
    float4* dst = (float4*)(out + ((size_t)b * kTOPK + k) * kD);
    dst[threadIdx.x] = src[threadIdx.x];     // 256 * 16B = 4KB = one row
}

// ---------------- launch ----------------
extern "C" void kernel_launch(void* const* d_in, const int* in_sizes, int n_in,
                              void* d_out, int out_size)
{
    (void)in_sizes; (void)n_in; (void)out_size;
    const float* tf  = (const float*)d_in[0];   // token_features  [8,4096,1024]
    const float* den = (const float*)d_in[1];   // token_densities [8,4096]
    const float* qe  = (const float*)d_in[2];   // query_embed     [64,1024]
    const float* kw  = (const float*)d_in[3];   // key_w           [1024,1024]
    const float* kb  = (const float*)d_in[4];   // key_b           [1024]
    const float* w1  = (const float*)d_in[5];   // de_w1           [1,2048]
    const float* b1  = (const float*)d_in[6];   // de_b1           [2048]
    const float* w2  = (const float*)d_in[7];   // de_w2           [2048,1]
    const float* b2  = (const float*)d_in[8];   // de_b2           [1]
    float* out = (float*)d_out;                 // [8,1024,1024] f32

    qw_kernel<<<kD / 128, 256>>>(kw, qe);
    qb_kernel<<<1, 64>>>(qe, kb);
    density_kernel<<<kB * kN / 256, 256>>>(den, w1, b1, w2, b2);
    scores_kernel<<<dim3(kN / 128, kB), 256>>>(tf);
    lse_kernel<<<kB * kNQ, 256>>>();
    logit_kernel<<<dim3(kN / 256, kB), 256>>>();
    topk_kernel<<<kB, 1024>>>();
    gather_kernel<<<dim3(kTOPK, kB), 256>>>(tf, out);
}

// round 2
// speedup vs baseline: 1.5001x; 1.5001x over previous
#include <cuda_runtime.h>

constexpr int kB = 8, kN = 4096, kD = 1024, kNQ = 64;
constexpr int kTOPK = 1024;
constexpr int KC = 16;     // K-chunk per smem stage
constexpr int AP = 132;    // smem pitch (floats)
constexpr int STG = KC * AP;

// ---------------- scratch (device globals; no allocations allowed) ----------------
__device__ float g_QW[kNQ * kD];            // (query_embed @ key_w^T) / sqrt(H)
__device__ float g_QWp[8 * kNQ * kD];       // split-K partials
__device__ float g_qb[kNQ];                 // (query_embed @ key_b) / sqrt(H)
__device__ float g_bias[kB * kN];           // density bias per token
__device__ float g_S[(size_t)kB * kNQ * kN];// scores [b][q][n]
__device__ float g_lse[kB * kNQ];           // logsumexp per (b,q)
__device__ float g_logit[kB * kN];          // max_q (s - lse) per token
__device__ int   g_idx[kB * kTOPK];         // selected indices, ascending

// ---------------- f32x2 packed-FP32 helpers (Blackwell FFMA2) ----------------
__device__ __forceinline__ void f32x2_unpack(unsigned long long v, float& lo, float& hi) {
    asm("mov.b64 {%0, %1}, %2;" : "=f"(lo), "=f"(hi) : "l"(v));
}
__device__ __forceinline__ unsigned long long f32x2_fma(unsigned long long a,
                                                        unsigned long long b,
                                                        unsigned long long c) {
    unsigned long long d;
    asm("fma.rn.f32x2 %0, %1, %2, %3;" : "=l"(d) : "l"(a), "l"(b), "l"(c));
    return d;
}

// ---------------- stage loaders for the 128x64 tile GEMM ----------------
// A tile: 128 rows x 16 k, stored TRANSPOSED As[k][row]  (row pairs -> f32x2 direct)
// B tile: 64 cols x 16 k, stored DUPLICATED Bs[k][2c..2c+1] = {B,B}
__device__ __forceinline__ void ldg_stage(const float* __restrict__ A,
                                          const float* __restrict__ Bm,
                                          int k0, float4 pa[2], float4& pb, int tid)
{
#pragma unroll
    for (int i = 0; i < 2; i++) {
        int idx = tid + i * 256;              // 512 float4 slots: r=idx>>2, c4=idx&3
        int r = idx >> 2, c4 = idx & 3;
        pa[i] = *(const float4*)(A + (size_t)r * kD + k0 + c4 * 4);
    }
    {
        int q = tid >> 2, c4 = tid & 3;       // 256 float4 slots
        pb = *(const float4*)(Bm + (size_t)q * kD + k0 + c4 * 4);
    }
}

__device__ __forceinline__ void sts_stage(float* As, float* Bs,
                                          const float4 pa[2], const float4& pb, int tid)
{
#pragma unroll
    for (int i = 0; i < 2; i++) {
        int idx = tid + i * 256;
        int r = idx >> 2, c4 = idx & 3;
        float* p = As + (c4 * 4) * AP + r;
        p[0] = pa[i].x; p[AP] = pa[i].y; p[2 * AP] = pa[i].z; p[3 * AP] = pa[i].w;
    }
    {
        int q = tid >> 2, c4 = tid & 3;
        float* p = Bs + (c4 * 4) * AP + 2 * q;
        p[0] = pb.x;          p[1] = pb.x;
        p[AP] = pb.y;         p[AP + 1] = pb.y;
        p[2 * AP] = pb.z;     p[2 * AP + 1] = pb.z;
        p[3 * AP] = pb.w;     p[3 * AP + 1] = pb.w;
    }
}

// C[r][c] = sum_{k in [kbeg,kend)} A[r][k] * Bm[c][k]; double-buffered.
// 256 threads: warp w -> cols 8w..8w+7; lane l -> rows 4l..4l+3 (as 2 f32x2 pairs).
__device__ __forceinline__ void gemm128x64(const float* __restrict__ A,
                                           const float* __restrict__ Bm,
                                           int kbeg, int kend,
                                           float* As, float* Bs,
                                           unsigned long long c2[2][8])
{
    const int tid = threadIdx.x;
    const int w = tid >> 5, l = tid & 31;
#pragma unroll
    for (int p = 0; p < 2; p++)
#pragma unroll
        for (int c = 0; c < 8; c++) c2[p][c] = 0ull;

    float4 pa[2]; float4 pb;
    ldg_stage(A, Bm, kbeg, pa, pb, tid);
    sts_stage(As, Bs, pa, pb, tid);
    __syncthreads();

    const int ns = (kend - kbeg) >> 4;
    for (int s = 0; s < ns; s++) {
        const float* Ac = As + (s & 1) * STG;
        const float* Bc = Bs + (s & 1) * STG;
        if (s + 1 < ns) ldg_stage(A, Bm, kbeg + (s + 1) * KC, pa, pb, tid);
#pragma unroll
        for (int k = 0; k < KC; k++) {
            ulonglong2 a = *(const ulonglong2*)(Ac + k * AP + 4 * l);
            const float* bp = Bc + k * AP + 16 * w;
            ulonglong2 b0 = *(const ulonglong2*)(bp);
            ulonglong2 b1 = *(const ulonglong2*)(bp + 4);
            ulonglong2 b2 = *(const ulonglong2*)(bp + 8);
            ulonglong2 b3 = *(const ulonglong2*)(bp + 12);
            c2[0][0] = f32x2_fma(a.x, b0.x, c2[0][0]);
            c2[0][1] = f32x2_fma(a.x, b0.y, c2[0][1]);
            c2[0][2] = f32x2_fma(a.x, b1.x, c2[0][2]);
            c2[0][3] = f32x2_fma(a.x, b1.y, c2[0][3]);
            c2[0][4] = f32x2_fma(a.x, b2.x, c2[0][4]);
            c2[0][5] = f32x2_fma(a.x, b2.y, c2[0][5]);
            c2[0][6] = f32x2_fma(a.x, b3.x, c2[0][6]);
            c2[0][7] = f32x2_fma(a.x, b3.y, c2[0][7]);
            c2[1][0] = f32x2_fma(a.y, b0.x, c2[1][0]);
            c2[1][1] = f32x2_fma(a.y, b0.y, c2[1][1]);
            c2[1][2] = f32x2_fma(a.y, b1.x, c2[1][2]);
            c2[1][3] = f32x2_fma(a.y, b1.y, c2[1][3]);
            c2[1][4] = f32x2_fma(a.y, b2.x, c2[1][4]);
            c2[1][5] = f32x2_fma(a.y, b2.y, c2[1][5]);
            c2[1][6] = f32x2_fma(a.y, b3.x, c2[1][6]);
            c2[1][7] = f32x2_fma(a.y, b3.y, c2[1][7]);
        }
        if (s + 1 < ns) {
            sts_stage(As + ((s + 1) & 1) * STG, Bs + ((s + 1) & 1) * STG, pa, pb, tid);
            __syncthreads();
        }
    }
}

// ---------------- 1) QW split-K partials: part[kc][q][d] ----------------
__global__ void __launch_bounds__(256, 2) qw_kernel(const float* __restrict__ kw,
                                                    const float* __restrict__ qe)
{
    __shared__ float As[2 * STG];
    __shared__ float Bs[2 * STG];
    const int d0 = blockIdx.x * 128;
    const int kc = blockIdx.y;
    unsigned long long c2[2][8];
    gemm128x64(kw + (size_t)d0 * kD, qe, kc * 128, kc * 128 + 128, As, Bs, c2);

    const int tid = threadIdx.x, w = tid >> 5, l = tid & 31;
    const int dbase = d0 + 4 * l;
    float* gp = g_QWp + (size_t)kc * (kNQ * kD);
#pragma unroll
    for (int c = 0; c < 8; c++) {
        const int q = 8 * w + c;
        float4 o;
        f32x2_unpack(c2[0][c], o.x, o.y);
        f32x2_unpack(c2[1][c], o.z, o.w);
        *(float4*)(gp + (size_t)q * kD + dbase) = o;
    }
}

// ---------------- 1b) reduce partials, scale 1/32 ----------------
__global__ void __launch_bounds__(256) qwred_kernel()
{
    const int i4 = blockIdx.x * 256 + threadIdx.x;     // 16384 float4
    float4 acc = make_float4(0.f, 0.f, 0.f, 0.f);
#pragma unroll
    for (int c = 0; c < 8; c++) {
        float4 v = ((const float4*)g_QWp)[(size_t)c * 16384 + i4];
        acc.x += v.x; acc.y += v.y; acc.z += v.z; acc.w += v.w;
    }
    acc.x *= 0.03125f; acc.y *= 0.03125f; acc.z *= 0.03125f; acc.w *= 0.03125f;
    ((float4*)g_QW)[i4] = acc;
}

// ---------------- 2) qb = (query_embed @ key_b)/32 ----------------
__global__ void qb_kernel(const float* __restrict__ qe, const float* __restrict__ kb)
{
    const int q = threadIdx.x;            // 64 threads
    const float* row = qe + (size_t)q * kD;
    float s0 = 0.f, s1 = 0.f, s2 = 0.f, s3 = 0.f;
    for (int h = 0; h < kD; h += 4) {
        s0 = fmaf(row[h + 0], kb[h + 0], s0);
        s1 = fmaf(row[h + 1], kb[h + 1], s1);
        s2 = fmaf(row[h + 2], kb[h + 2], s2);
        s3 = fmaf(row[h + 3], kb[h + 3], s3);
    }
    g_qb[q] = ((s0 + s1) + (s2 + s3)) * 0.03125f;
}

// ---------------- 3) density bias: relu(d*w1 + b1) @ w2 + b2 ----------------
__global__ void __launch_bounds__(256) density_kernel(
    const float* __restrict__ dens, const float* __restrict__ w1,
    const float* __restrict__ b1, const float* __restrict__ w2,
    const float* __restrict__ b2)
{
    __shared__ float4 sw1[512], sb1[512], sw2[512];
    const int tid = threadIdx.x;
    for (int i = tid; i < 512; i += 256) {
        sw1[i] = ((const float4*)w1)[i];
        sb1[i] = ((const float4*)b1)[i];
        sw2[i] = ((const float4*)w2)[i];
    }
    __syncthreads();
    const int t = blockIdx.x * 256 + tid;
    const float d = dens[t];
    float a0 = 0.f, a1 = 0.f, a2 = 0.f, a3 = 0.f;
#pragma unroll 4
    for (int j = 0; j < 512; j++) {
        float4 w = sw1[j], bb = sb1[j], v = sw2[j];
        float h0 = fmaxf(fmaf(d, w.x, bb.x), 0.f);
        float h1 = fmaxf(fmaf(d, w.y, bb.y), 0.f);
        float h2 = fmaxf(fmaf(d, w.z, bb.z), 0.f);
        float h3 = fmaxf(fmaf(d, w.w, bb.w), 0.f);
        a0 = fmaf(h0, v.x, a0);
        a1 = fmaf(h1, v.y, a1);
        a2 = fmaf(h2, v.z, a2);
        a3 = fmaf(h3, v.w, a3);
    }
    g_bias[t] = (a0 + a1) + (a2 + a3) + b2[0];
}

// ---------------- 4) scores S[b][q][n] = tf·QW^T + qb + bias ----------------
__global__ void __launch_bounds__(256, 2) scores_kernel(const float* __restrict__ tf)
{
    __shared__ float As[2 * STG];
    __shared__ float Bs[2 * STG];
    const int b = blockIdx.y;
    const int n0 = blockIdx.x * 128;
    unsigned long long c2[2][8];
    gemm128x64(tf + ((size_t)b * kN + n0) * kD, g_QW, 0, kD, As, Bs, c2);

    const int tid = threadIdx.x, w = tid >> 5, l = tid & 31;
    const int nbase = n0 + 4 * l;
    float bv[4];
#pragma unroll
    for (int j = 0; j < 4; j++) bv[j] = g_bias[b * kN + nbase + j];
#pragma unroll
    for (int c = 0; c < 8; c++) {
        const int q = 8 * w + c;
        const float add = g_qb[q];
        float4 o;
        f32x2_unpack(c2[0][c], o.x, o.y);
        f32x2_unpack(c2[1][c], o.z, o.w);
        o.x += add + bv[0];
        o.y += add + bv[1];
        o.z += add + bv[2];
        o.w += add + bv[3];
        *(float4*)(g_S + ((size_t)(b * kNQ + q)) * kN + nbase) = o;
    }
}

// ---------------- 5) per-(b,q) logsumexp over n ----------------
__global__ void __launch_bounds__(256) lse_kernel()
{
    const int row = blockIdx.x;           // 0..511
    const float4* s4 = (const float4*)(g_S + (size_t)row * kN);
    const int tid = threadIdx.x;
    __shared__ float red[8];

    float m = -3.402823466e38f;
    for (int i = tid; i < kN / 4; i += 256) {
        float4 v = s4[i];
        m = fmaxf(m, fmaxf(fmaxf(v.x, v.y), fmaxf(v.z, v.w)));
    }
#pragma unroll
    for (int o = 16; o; o >>= 1) m = fmaxf(m, __shfl_xor_sync(0xffffffffu, m, o));
    if ((tid & 31) == 0) red[tid >> 5] = m;
    __syncthreads();
    float mm = red[0];
#pragma unroll
    for (int i = 1; i < 8; i++) mm = fmaxf(mm, red[i]);
    __syncthreads();

    float sum = 0.f;
    for (int i = tid; i < kN / 4; i += 256) {
        float4 v = s4[i];
        sum += __expf(v.x - mm) + __expf(v.y - mm) + __expf(v.z - mm) + __expf(v.w - mm);
    }
#pragma unroll
    for (int o = 16; o; o >>= 1) sum += __shfl_xor_sync(0xffffffffu, sum, o);
    if ((tid & 31) == 0) red[tid >> 5] = sum;
    __syncthreads();
    if (tid == 0) {
        float tot = red[0];
        for (int i = 1; i < 8; i++) tot += red[i];
        g_lse[row] = mm + logf(tot);
    }
}

// ---------------- 6) importance logit = max_q (s - lse) ----------------
__global__ void __launch_bounds__(256) logit_kernel()
{
    __shared__ float ls[kNQ];
    const int tid = threadIdx.x;
    const int b = blockIdx.y;
    if (tid < kNQ) ls[tid] = g_lse[b * kNQ + tid];
    __syncthreads();
    const int n = blockIdx.x * 256 + tid;
    const float* s = g_S + (size_t)b * kNQ * kN + n;
    float best = -3.402823466e38f;
#pragma unroll 8
    for (int q = 0; q < kNQ; q++)
        best = fmaxf(best, s[(size_t)q * kN] - ls[q]);
    g_logit[b * kN + n] = best;
}

// ---------------- 7) per-batch top-1024 via radix select + tie-aware compaction ----------------
__global__ void __launch_bounds__(1024) topk_kernel()
{
    const int b = blockIdx.x;
    const int tid = threadIdx.x;
    __shared__ unsigned su[kN];
    __shared__ int hist[256];
    __shared__ int sc[256];
    __shared__ int s_need, s_digit;
    __shared__ int wsum[32];
    const float* lg = g_logit + b * kN;

    // order-preserving float->uint transform (finite values only)
    for (int i = tid; i < kN; i += 1024) {
        unsigned x = __float_as_uint(lg[i]);
        su[i] = (x & 0x80000000u) ? ~x : (x ^ 0x80000000u);
    }
    if (tid == 0) s_need = kTOPK;

    unsigned prefix = 0, pmask = 0;
    for (int pass = 0; pass < 4; pass++) {
        const int shift = 24 - 8 * pass;
        if (tid < 256) hist[tid] = 0;
        __syncthreads();
        const int need = s_need;              // stable: written last pass, barriers since
        for (int i = tid; i < kN; i += 1024) {
            unsigned u = su[i];
            if ((u & pmask) == prefix) atomicAdd(&hist[(u >> shift) & 255], 1);
        }
        __syncthreads();
        // reverse inclusive scan: sc[t] = sum_{d >= 255-t} hist[d]
        if (tid < 256) sc[tid] = hist[255 - tid];
        __syncthreads();
        for (int off = 1; off < 256; off <<= 1) {
            int v = 0;
            if (tid < 256 && tid >= off) v = sc[tid - off];
            __syncthreads();
            if (tid < 256) sc[tid] += v;
            __syncthreads();
        }
        if (tid < 256) {
            int incl = sc[tid];
            int excl = (tid == 0) ? 0 : sc[tid - 1];
            if (incl >= need && excl < need) {
                s_digit = 255 - tid;
                s_need = need - excl;
            }
        }
        __syncthreads();
        prefix |= ((unsigned)s_digit) << shift;
        pmask |= 0xFFu << shift;
        __syncthreads();
    }
    // reconstruct threshold float (k-th largest value)
    const unsigned ut = prefix;
    const float thr = __uint_as_float((ut & 0x80000000u) ? (ut ^ 0x80000000u) : ~ut);

    // tie-aware compaction (ties filled by lowest index = jax top_k semantics)
    float v[4];
    int gt = 0, eq = 0;
#pragma unroll
    for (int u = 0; u < 4; u++) {
        v[u] = lg[tid * 4 + u];
        gt += (v[u] > thr);
        eq += (v[u] == thr);
    }
    int x = (gt << 16) | eq;
    const int lane = tid & 31, wid = tid >> 5;
#pragma unroll
    for (int o = 1; o < 32; o <<= 1) {
        int y = __shfl_up_sync(0xffffffffu, x, o);
        if (lane >= o) x += y;
    }
    if (lane == 31) wsum[wid] = x;
    __syncthreads();
    if (wid == 0) {
        int y = wsum[lane];
#pragma unroll
        for (int o = 1; o < 32; o <<= 1) {
            int z = __shfl_up_sync(0xffffffffu, y, o);
            if (lane >= o) y += z;
        }
        wsum[lane] = y;
    }
    __syncthreads();
    const int warpbase = (wid == 0) ? 0 : wsum[wid - 1];
    const int incl = warpbase + x;
    int gt_before = (incl >> 16) - gt;
    int eq_before = (incl & 0xffff) - eq;
    const int total_gt = wsum[31] >> 16;
    const int need_eq = kTOPK - total_gt;
    int* outi = g_idx + b * kTOPK;
#pragma unroll
    for (int u = 0; u < 4; u++) {
        const int n = tid * 4 + u;
        if (v[u] > thr) {
            int pos = gt_before + min(eq_before, need_eq);
            outi[pos] = n;
            gt_before++;
        } else if (v[u] == thr) {
            if (eq_before < need_eq) outi[gt_before + eq_before] = n;
            eq_before++;
        }
    }
}

// ---------------- 8) gather selected rows ----------------
__global__ void __launch_bounds__(256) gather_kernel(const float* __restrict__ tf,
                                                     float* __restrict__ out)
{
    const int b = blockIdx.y, k = blockIdx.x;
    const int row = g_idx[b * kTOPK + k];
    const float4* src = (const float4*)(tf + ((size_t)b * kN + row) * kD);
    float4* dst = (float4*)(out + ((size_t)b * kTOPK + k) * kD);
    dst[threadIdx.x] = src[threadIdx.x];     // 256 * 16B = 4KB = one row
}

// ---------------- launch ----------------
extern "C" void kernel_launch(void* const* d_in, const int* in_sizes, int n_in,
                              void* d_out, int out_size)
{
    (void)in_sizes; (void)n_in; (void)out_size;
    const float* tf  = (const float*)d_in[0];   // token_features  [8,4096,1024]
    const float* den = (const float*)d_in[1];   // token_densities [8,4096]
    const float* qe  = (const float*)d_in[2];   // query_embed     [64,1024]
    const float* kw  = (const float*)d_in[3];   // key_w           [1024,1024]
    const float* kb  = (const float*)d_in[4];   // key_b           [1024]
    const float* w1  = (const float*)d_in[5];   // de_w1           [1,2048]
    const float* b1  = (const float*)d_in[6];   // de_b1           [2048]
    const float* w2  = (const float*)d_in[7];   // de_w2           [2048,1]
    const float* b2  = (const float*)d_in[8];   // de_b2           [1]
    float* out = (float*)d_out;                 // [8,1024,1024] f32

    qw_kernel<<<dim3(kD / 128, 8), 256>>>(kw, qe);
    qwred_kernel<<<64, 256>>>();
    qb_kernel<<<1, 64>>>(qe, kb);
    density_kernel<<<kB * kN / 256, 256>>>(den, w1, b1, w2, b2);
    scores_kernel<<<dim3(kN / 128, kB), 256>>>(tf);
    lse_kernel<<<kB * kNQ, 256>>>();
    logit_kernel<<<dim3(kN / 256, kB), 256>>>();
    topk_kernel<<<kB, 1024>>>();
    gather_kernel<<<dim3(kTOPK, kB), 256>>>(tf, out);
}